// round 7
// baseline (speedup 1.0000x reference)
#include <cuda_runtime.h>
#include <math.h>

#define NMAX 200000
#define DFEAT 256
#define MNB   64
#define KSEL  3
#define NODES_PER_WARP 8

// Scratch (allocation-free): per-node projections.
__device__ float g_s_self[NMAX];
__device__ float g_s_all[NMAX];

// ---------------------------------------------------------------------------
// Kernel 1: one warp handles 8 nodes as two software-pipelined batches of 4.
// Batch i+1's eight LDG.128 are issued BEFORE batch i's FMA + reduction
// window, keeping DRAM fed through compute. Reduction = 4 independent
// interleaved butterflies (8 shfls/level, fully overlapped latencies).
// ---------------------------------------------------------------------------
__global__ void __launch_bounds__(256) score_kernel(const float* __restrict__ x,
                                                    const float* __restrict__ W,
                                                    const float* __restrict__ bias,
                                                    int N) {
    int warp = (blockIdx.x * 256 + threadIdx.x) >> 5;
    int lane = threadIdx.x & 31;
    int node0 = warp * NODES_PER_WARP;
    if (node0 >= N) return;

    const float4* wa4 = (const float4*)(W);          // W[0:256]
    const float4* wb4 = (const float4*)(W + DFEAT);  // W[256:512]
    float4 a0 = __ldg(wa4 + lane), a1 = __ldg(wa4 + lane + 32);
    float4 b0 = __ldg(wb4 + lane), b1 = __ldg(wb4 + lane + 32);
    float bb = bias[0];

    float4 cur0[4], cur1[4];
#pragma unroll
    for (int i = 0; i < 4; i++) {
        int n = node0 + i;
        if (n < N) {
            const float4* xr = (const float4*)(x + (size_t)n * DFEAT);
            cur0[i] = __ldg(xr + lane);
            cur1[i] = __ldg(xr + lane + 32);
        }
    }

#pragma unroll
    for (int batch = 0; batch < NODES_PER_WARP; batch += 4) {
        int nb0 = node0 + batch;

        float4 nxt0[4], nxt1[4];
        if (batch + 4 < NODES_PER_WARP) {            // prefetch next batch
#pragma unroll
            for (int i = 0; i < 4; i++) {
                int n = nb0 + 4 + i;
                if (n < N) {
                    const float4* xr = (const float4*)(x + (size_t)n * DFEAT);
                    nxt0[i] = __ldg(xr + lane);
                    nxt1[i] = __ldg(xr + lane + 32);
                }
            }
        }

        float sa[4], sb[4];
#pragma unroll
        for (int i = 0; i < 4; i++) {
            float4 c0 = cur0[i], c1 = cur1[i];
            float ta, tb;
            ta  = c0.x * a0.x;          ta = fmaf(c0.y, a0.y, ta);
            ta  = fmaf(c0.z, a0.z, ta); ta = fmaf(c0.w, a0.w, ta);
            ta  = fmaf(c1.x, a1.x, ta); ta = fmaf(c1.y, a1.y, ta);
            ta  = fmaf(c1.z, a1.z, ta); ta = fmaf(c1.w, a1.w, ta);
            tb  = c0.x * b0.x;          tb = fmaf(c0.y, b0.y, tb);
            tb  = fmaf(c0.z, b0.z, tb); tb = fmaf(c0.w, b0.w, tb);
            tb  = fmaf(c1.x, b1.x, tb); tb = fmaf(c1.y, b1.y, tb);
            tb  = fmaf(c1.z, b1.z, tb); tb = fmaf(c1.w, b1.w, tb);
            sa[i] = ta; sb[i] = tb;
        }

        // 4 independent interleaved butterflies (8 shfls per level).
#pragma unroll
        for (int off = 16; off; off >>= 1) {
#pragma unroll
            for (int i = 0; i < 4; i++) {
                sa[i] += __shfl_xor_sync(0xffffffffu, sa[i], off);
                sb[i] += __shfl_xor_sync(0xffffffffu, sb[i], off);
            }
        }
        if (lane == 0) {
#pragma unroll
            for (int i = 0; i < 4; i++) {
                int n = nb0 + i;
                if (n < N) {
                    g_s_self[n] = sa[i] + bb;
                    g_s_all[n]  = sb[i];
                }
            }
        }

        if (batch + 4 < NODES_PER_WARP) {
#pragma unroll
            for (int i = 0; i < 4; i++) { cur0[i] = nxt0[i]; cur1[i] = nxt1[i]; }
        }
    }
}

// Order-preserving float<->uint mapping (total order on floats).
__device__ __forceinline__ unsigned fkey(float f) {
    unsigned u = __float_as_uint(f);
    return (u & 0x80000000u) ? ~u : (u | 0x80000000u);
}
__device__ __forceinline__ float funkey(unsigned u) {
    unsigned b = (u & 0x80000000u) ? (u & 0x7fffffffu) : ~u;
    return __uint_as_float(b);
}

// ---------------------------------------------------------------------------
// Kernel 2 (unchanged from best measured variant): TWO nodes per warp
// (16-lane segments), 4 candidate slots/lane. Per-lane presort (5 keyed
// compare-swaps), then 3 rounds touching only the per-lane HEAD: REDUX.max +
// ballot + ffs; the winning lane stores the selected id DIRECTLY and pops.
// Values written by lanes 0..2 with __expf. Gathers predicated on cnt
// (halves L1 wavefronts); neighbor int4 load unconditional (DRAM has slack).
// ---------------------------------------------------------------------------
__global__ void __launch_bounds__(256) topk_kernel(const int* __restrict__ neighbors,
                                                   const int* __restrict__ counts,
                                                   float* __restrict__ out,
                                                   int N) {
    int warp = (blockIdx.x * 256 + threadIdx.x) >> 5;
    int lane = threadIdx.x & 31;
    int half = lane >> 4;                 // segment id within warp
    int sub  = lane & 15;                 // lane within segment
    int node = warp * 2 + half;
    if (node >= N) return;

    unsigned mask = half ? 0xFFFF0000u : 0x0000FFFFu;

    int cnt  = __ldg(counts + node);
    int base = sub * 4;

    const int4* nb = (const int4*)(neighbors + (size_t)node * MNB);
    int4 nbr = __ldg(nb + sub);            // indices always valid node ids

    // key 0 marks invalid; fkey(any float) > 0. Predicated-off gathers emit
    // no L1 wavefront (load-bearing for the memory floor). cnt >= K.
    unsigned k0 = (base + 0 < cnt) ? fkey(__ldg(g_s_all + nbr.x)) : 0u;
    unsigned k1 = (base + 1 < cnt) ? fkey(__ldg(g_s_all + nbr.y)) : 0u;
    unsigned k2 = (base + 2 < cnt) ? fkey(__ldg(g_s_all + nbr.z)) : 0u;
    unsigned k3 = (base + 3 < cnt) ? fkey(__ldg(g_s_all + nbr.w)) : 0u;
    int c0 = nbr.x, c1 = nbr.y, c2 = nbr.z, c3 = nbr.w;

    // Presort the 4 (key,cand) pairs descending by key.
#define CSWAP(ka, ca, kb, cb)                                        \
    { bool sw = (kb) > (ka);                                         \
      unsigned tk = sw ? (kb) : (ka); (kb) = sw ? (ka) : (kb); (ka) = tk; \
      int tc = sw ? (cb) : (ca); (cb) = sw ? (ca) : (cb); (ca) = tc; }
    CSWAP(k0, c0, k1, c1)
    CSWAP(k2, c2, k3, c3)
    CSWAP(k0, c0, k2, c2)
    CSWAP(k1, c1, k3, c3)
    CSWAP(k1, c1, k2, c2)
#undef CSWAP

    float* osel = out + (size_t)N * KSEL;
    size_t ob = (size_t)node * KSEL;

    unsigned w0, w1, w2;
#pragma unroll
    for (int t = 0; t < KSEL; t++) {
        unsigned m = __reduce_max_sync(mask, k0);
        unsigned bal = __ballot_sync(mask, k0 == m);   // non-mask bits are 0
        int wl = __ffs((int)bal) - 1;                  // absolute lane id

        if (t == 0) w0 = m; else if (t == 1) w1 = m; else w2 = m;

        if (lane == wl) {                              // winner: store id, pop
            osel[ob + t] = (float)c0;                  // exact: ids < 2^24
            k0 = k1; c0 = c1;
            k1 = k2; c1 = c2;
            k2 = k3; c2 = c3;
        }
    }

    if (sub < KSEL) {                                  // parallel value epilogue
        unsigned wk = (sub == 0) ? w0 : (sub == 1) ? w1 : w2;
        float v = g_s_self[node] + funkey(wk);
        v = fmaxf(v, 0.01f * v);                       // leaky_relu (jax default)
        out[ob + sub] = __expf(v);
    }
}

extern "C" void kernel_launch(void* const* d_in, const int* in_sizes, int n_in,
                              void* d_out, int out_size) {
    // metadata order: node_features, neighbors, neighbor_counts, W, b
    const float* x         = (const float*)d_in[0];
    const int*   neighbors = (const int*)d_in[1];
    const int*   counts    = (const int*)d_in[2];
    const float* W         = (const float*)d_in[3];
    const float* bias      = (const float*)d_in[4];

    int N = in_sizes[0] / DFEAT;
    if (N > NMAX) N = NMAX;

    int warps1  = (N + NODES_PER_WARP - 1) / NODES_PER_WARP;
    int blocks1 = (warps1 + 7) / 8;
    score_kernel<<<blocks1, 256>>>(x, W, bias, N);

    int warps2  = (N + 1) / 2;               // 2 nodes per warp
    int blocks2 = (warps2 + 7) / 8;
    topk_kernel<<<blocks2, 256>>>(neighbors, counts, (float*)d_out, N);
}

// round 8
// speedup vs baseline: 1.1550x; 1.1550x over previous
#include <cuda_runtime.h>
#include <math.h>

#define NMAX 200000
#define DFEAT 256
#define MNB   64
#define KSEL  3
#define NODES_PER_WARP 8

// Scratch (allocation-free): per-node projections.
__device__ float g_s_self[NMAX];
__device__ float g_s_all[NMAX];

// ---------------------------------------------------------------------------
// Kernel 1 (reverted to round-4/5 measured optimum): one warp handles 8 nodes
// in 2 batches of 4. All 4 rows of a batch loaded up-front (8 LDG.128/lane in
// flight), then 4 independent interleaved butterfly reductions (8 shfls per
// level, overlapped latencies). No cross-batch pipelining (register cliff).
// ---------------------------------------------------------------------------
__global__ void __launch_bounds__(256) score_kernel(const float* __restrict__ x,
                                                    const float* __restrict__ W,
                                                    const float* __restrict__ bias,
                                                    int N) {
    int warp = (blockIdx.x * 256 + threadIdx.x) >> 5;
    int lane = threadIdx.x & 31;
    int node0 = warp * NODES_PER_WARP;
    if (node0 >= N) return;

    const float4* wa4 = (const float4*)(W);          // W[0:256]
    const float4* wb4 = (const float4*)(W + DFEAT);  // W[256:512]
    float4 a0 = __ldg(wa4 + lane), a1 = __ldg(wa4 + lane + 32);
    float4 b0 = __ldg(wb4 + lane), b1 = __ldg(wb4 + lane + 32);
    float bb = bias[0];

#pragma unroll
    for (int batch = 0; batch < NODES_PER_WARP; batch += 4) {
        int nb0 = node0 + batch;

        float4 v0[4], v1[4];
#pragma unroll
        for (int i = 0; i < 4; i++) {
            int n = nb0 + i;
            if (n < N) {
                const float4* xr = (const float4*)(x + (size_t)n * DFEAT);
                v0[i] = __ldg(xr + lane);
                v1[i] = __ldg(xr + lane + 32);
            }
        }

        float sa[4], sb[4];
#pragma unroll
        for (int i = 0; i < 4; i++) {
            float4 c0 = v0[i], c1 = v1[i];
            float ta, tb;
            ta  = c0.x * a0.x;          ta = fmaf(c0.y, a0.y, ta);
            ta  = fmaf(c0.z, a0.z, ta); ta = fmaf(c0.w, a0.w, ta);
            ta  = fmaf(c1.x, a1.x, ta); ta = fmaf(c1.y, a1.y, ta);
            ta  = fmaf(c1.z, a1.z, ta); ta = fmaf(c1.w, a1.w, ta);
            tb  = c0.x * b0.x;          tb = fmaf(c0.y, b0.y, tb);
            tb  = fmaf(c0.z, b0.z, tb); tb = fmaf(c0.w, b0.w, tb);
            tb  = fmaf(c1.x, b1.x, tb); tb = fmaf(c1.y, b1.y, tb);
            tb  = fmaf(c1.z, b1.z, tb); tb = fmaf(c1.w, b1.w, tb);
            sa[i] = ta; sb[i] = tb;
        }

        // 4 independent interleaved butterflies (8 shfls per level).
#pragma unroll
        for (int off = 16; off; off >>= 1) {
#pragma unroll
            for (int i = 0; i < 4; i++) {
                sa[i] += __shfl_xor_sync(0xffffffffu, sa[i], off);
                sb[i] += __shfl_xor_sync(0xffffffffu, sb[i], off);
            }
        }
        if (lane == 0) {
#pragma unroll
            for (int i = 0; i < 4; i++) {
                int n = nb0 + i;
                if (n < N) {
                    g_s_self[n] = sa[i] + bb;
                    g_s_all[n]  = sb[i];
                }
            }
        }
    }
}

// Order-preserving float<->uint mapping (total order on floats).
__device__ __forceinline__ unsigned fkey(float f) {
    unsigned u = __float_as_uint(f);
    return (u & 0x80000000u) ? ~u : (u | 0x80000000u);
}
__device__ __forceinline__ float funkey(unsigned u) {
    unsigned b = (u & 0x80000000u) ? (u & 0x7fffffffu) : ~u;
    return __uint_as_float(b);
}

// ---------------------------------------------------------------------------
// Kernel 2: FOUR nodes per warp (8-lane segments), 8 candidate slots/lane.
// Per-lane Batcher-8 presort (19 compare-swaps) descending; 3 rounds touch
// only the per-lane HEAD: segmented REDUX.max + ballot + ffs; the winning
// lane stores the selected id DIRECTLY and pops its head. Values written by
// segment-lanes 0..2 with __expf. Gathers predicated on cnt (saves L1
// wavefronts); neighbor int4 loads unconditional (DRAM has slack).
// ---------------------------------------------------------------------------
__global__ void __launch_bounds__(256) topk_kernel(const int* __restrict__ neighbors,
                                                   const int* __restrict__ counts,
                                                   float* __restrict__ out,
                                                   int N) {
    int warp = (blockIdx.x * 256 + threadIdx.x) >> 5;
    int lane = threadIdx.x & 31;
    int seg  = lane >> 3;                 // segment id within warp (0..3)
    int sub  = lane & 7;                  // lane within segment
    int node = warp * 4 + seg;
    if (node >= N) return;

    unsigned mask = 0xFFu << (seg * 8);

    int cnt  = __ldg(counts + node);
    int base = sub * 8;

    const int4* nb = (const int4*)(neighbors + (size_t)node * MNB);
    int4 nA = __ldg(nb + sub * 2);         // positions base..base+3
    int4 nB = __ldg(nb + sub * 2 + 1);     // positions base+4..base+7

    unsigned k[8];
    int      c[8];
    c[0] = nA.x; c[1] = nA.y; c[2] = nA.z; c[3] = nA.w;
    c[4] = nB.x; c[5] = nB.y; c[6] = nB.z; c[7] = nB.w;
    // key 0 marks invalid; fkey(any float) > 0. Predicated-off gathers emit
    // no L1 wavefront. cnt >= K so the top-3 are always real entries.
#pragma unroll
    for (int i = 0; i < 8; i++)
        k[i] = (base + i < cnt) ? fkey(__ldg(g_s_all + c[i])) : 0u;

    // Batcher odd-even mergesort for 8, descending (max kept at lower index).
#define CSWAP(i, j)                                                     \
    { bool sw = k[j] > k[i];                                            \
      unsigned tk = sw ? k[j] : k[i]; k[j] = sw ? k[i] : k[j]; k[i] = tk; \
      int tc = sw ? c[j] : c[i]; c[j] = sw ? c[i] : c[j]; c[i] = tc; }
    CSWAP(0,1) CSWAP(2,3) CSWAP(4,5) CSWAP(6,7)
    CSWAP(0,2) CSWAP(1,3) CSWAP(4,6) CSWAP(5,7)
    CSWAP(1,2) CSWAP(5,6)
    CSWAP(0,4) CSWAP(1,5) CSWAP(2,6) CSWAP(3,7)
    CSWAP(2,4) CSWAP(3,5)
    CSWAP(1,2) CSWAP(3,4) CSWAP(5,6)
#undef CSWAP

    float* osel = out + (size_t)N * KSEL;
    size_t ob = (size_t)node * KSEL;

    unsigned w0, w1, w2;
#pragma unroll
    for (int t = 0; t < KSEL; t++) {
        unsigned m = __reduce_max_sync(mask, k[0]);
        unsigned bal = __ballot_sync(mask, k[0] == m);  // non-mask bits are 0
        int wl = __ffs((int)bal) - 1;                   // absolute lane id

        if (t == 0) w0 = m; else if (t == 1) w1 = m; else w2 = m;

        if (lane == wl) {                               // winner: store id, pop
            osel[ob + t] = (float)c[0];                 // exact: ids < 2^24
#pragma unroll
            for (int i = 0; i < 7; i++) { k[i] = k[i + 1]; c[i] = c[i + 1]; }
        }
    }

    if (sub < KSEL) {                                   // parallel value epilogue
        unsigned wk = (sub == 0) ? w0 : (sub == 1) ? w1 : w2;
        float v = g_s_self[node] + funkey(wk);
        v = fmaxf(v, 0.01f * v);                        // leaky_relu (jax default)
        out[ob + sub] = __expf(v);
    }
}

extern "C" void kernel_launch(void* const* d_in, const int* in_sizes, int n_in,
                              void* d_out, int out_size) {
    // metadata order: node_features, neighbors, neighbor_counts, W, b
    const float* x         = (const float*)d_in[0];
    const int*   neighbors = (const int*)d_in[1];
    const int*   counts    = (const int*)d_in[2];
    const float* W         = (const float*)d_in[3];
    const float* bias      = (const float*)d_in[4];

    int N = in_sizes[0] / DFEAT;
    if (N > NMAX) N = NMAX;

    int warps1  = (N + NODES_PER_WARP - 1) / NODES_PER_WARP;
    int blocks1 = (warps1 + 7) / 8;
    score_kernel<<<blocks1, 256>>>(x, W, bias, N);

    int warps2  = (N + 3) / 4;               // 4 nodes per warp
    int blocks2 = (warps2 + 7) / 8;
    topk_kernel<<<blocks2, 256>>>(neighbors, counts, (float*)d_out, N);
}